// round 2
// baseline (speedup 1.0000x reference)
#include <cuda_runtime.h>

// ---------------- problem constants ----------------
#define CC 8
#define KK 1024
#define DD 32
#define NN 4096
#define NT 8
#define TILES 512          // NN / NT
#define THREADS 256
#define CB_STRIDE 33       // padded row stride for codebook in smem

// ---------------- smem layout (float offsets) ----------------
#define OFF_CB    0
#define OFF_CBSQ  (1024*33)            // 33792
#define OFF_DS    (OFF_CBSQ + 1024)    // 34816  (16B aligned: *4 % 16 == 0)
#define OFF_ZF    (OFF_DS + 8192)      // 43008
#define OFF_ZSQ   (OFF_ZF + 256)       // 43264
#define OFF_RED   (OFF_ZSQ + 16)       // 43280
#define OFF_QBAR  (OFF_RED + 2048)     // 45328
#define OFF_SCR   (OFF_QBAR + 1024)    // 46352
#define OFF_IDX   (OFF_SCR + 16)       // 46368 (ints, 8)
#define SMEM_FLOATS (OFF_IDX + 8)      // 46376
#define SMEM_BYTES (SMEM_FLOATS * 4)   // 185504 B

// ---------------- output packing (float32, tuple order) ----------------
#define O_QUANT 0u
#define O_IDX   1048576u
#define O_Q     1081344u
#define O_SC    34635776u

// ---------------- scratch ----------------
__device__ float g_qbar[CC * KK];
__device__ float g_comm;
__device__ float g_ne;
__device__ float g_qd;

__global__ void lgq_zero() {
    int t = blockIdx.x * blockDim.x + threadIdx.x;
    if (t < CC * KK) g_qbar[t] = 0.0f;
    if (t == 0) { g_comm = 0.0f; g_ne = 0.0f; g_qd = 0.0f; }
}

__global__ void __launch_bounds__(THREADS, 1)
lgq_main(const float* __restrict__ z, const float* __restrict__ cbg,
         float* __restrict__ out)
{
    extern __shared__ float sm[];
    float* cb_s = sm + OFF_CB;
    float* cbsq = sm + OFF_CBSQ;
    float* ds   = sm + OFF_DS;    // [8][1024] dists, later q
    float* zf   = sm + OFF_ZF;    // [8][32]
    float* zsq  = sm + OFF_ZSQ;   // [8]
    float* red  = sm + OFF_RED;   // [8 warps][8 n][32 j]
    float* qba  = sm + OFF_QBAR;  // [1024]
    float* scr  = sm + OFF_SCR;   // [8]
    int*   idxs = (int*)(sm + OFF_IDX);

    const int t    = threadIdx.x;
    const int w    = t >> 5;
    const int lane = t & 31;
    const int c    = blockIdx.y;

    // ---- stage codebook c (k-major, padded stride 33) ----
    const float4* cb4 = (const float4*)(cbg + (size_t)c * (KK * DD));
    for (int i = t; i < KK * DD / 4; i += THREADS) {
        float4 v = cb4[i];
        int k = i >> 3, j = (i & 7) << 2;
        float* p = cb_s + k * CB_STRIDE + j;
        p[0] = v.x; p[1] = v.y; p[2] = v.z; p[3] = v.w;
    }
    #pragma unroll
    for (int m = 0; m < 4; m++) qba[t + 256 * m] = 0.0f;
    __syncthreads();

    // ---- codeword squared norms ----
    #pragma unroll
    for (int m = 0; m < 4; m++) {
        int k = t + 256 * m;
        const float* p = cb_s + k * CB_STRIDE;
        float s = 0.0f;
        #pragma unroll
        for (int j = 0; j < 32; j++) s += p[j] * p[j];
        cbsq[k] = s;
    }
    __syncthreads();

    float ct_comm = 0.0f;             // per-thread commitment partial
    float acc_ne = 0.0f, acc_qd = 0.0f; // lane0-of-warp accumulators

    for (int tile = blockIdx.x; tile < TILES; tile += gridDim.x) {
        const int nb = tile * NT;

        // ---- stage zf tile: thread -> (j = t>>3, ni = t&7) coalesced in n ----
        {
            int j = t >> 3, ni = t & 7;
            int n = nb + ni;
            int b = n >> 10;
            zf[ni * 32 + j] = z[(size_t)(b * 256 + c * 32 + j) * 1024 + (n & 1023)];
        }
        __syncthreads();
        if (t < 8) {
            const float* p = zf + t * 32;
            float s = 0.0f;
            #pragma unroll
            for (int j = 0; j < 32; j++) s += p[j] * p[j];
            zsq[t] = s;
        }
        __syncthreads();

        // ---- phase 1: distances. thread owns all 8 n, k = t + 256m ----
        {
            float acc[8][4];
            #pragma unroll
            for (int n = 0; n < 8; n++)
                #pragma unroll
                for (int m = 0; m < 4; m++) acc[n][m] = 0.0f;

            const float4* zf4 = (const float4*)zf;
            #pragma unroll
            for (int j4 = 0; j4 < 8; j4++) {
                float cbv[4][4];
                #pragma unroll
                for (int m = 0; m < 4; m++) {
                    const float* p = cb_s + (t + 256 * m) * CB_STRIDE + j4 * 4;
                    cbv[m][0] = p[0]; cbv[m][1] = p[1];
                    cbv[m][2] = p[2]; cbv[m][3] = p[3];
                }
                #pragma unroll
                for (int n = 0; n < 8; n++) {
                    float4 zv = zf4[n * 8 + j4];
                    #pragma unroll
                    for (int m = 0; m < 4; m++) {
                        acc[n][m] = fmaf(zv.x, cbv[m][0], acc[n][m]);
                        acc[n][m] = fmaf(zv.y, cbv[m][1], acc[n][m]);
                        acc[n][m] = fmaf(zv.z, cbv[m][2], acc[n][m]);
                        acc[n][m] = fmaf(zv.w, cbv[m][3], acc[n][m]);
                    }
                }
            }
            float cq[4];
            #pragma unroll
            for (int m = 0; m < 4; m++) cq[m] = cbsq[t + 256 * m];
            #pragma unroll
            for (int n = 0; n < 8; n++) {
                float zq_ = zsq[n];
                #pragma unroll
                for (int m = 0; m < 4; m++)
                    ds[n * 1024 + t + 256 * m] = (zq_ - 2.0f * acc[n][m]) + cq[m];
            }
        }
        __syncthreads();

        // ---- phase 2: per-warp softmax / argmin for n = nb + w ----
        {
            const float4* row4  = (const float4*)(ds + w * 1024);
            float4*       row4w = (float4*)(ds + w * 1024);
            float dv[32];
            #pragma unroll
            for (int m4 = 0; m4 < 8; m4++) {
                float4 v = row4[lane + 32 * m4];
                dv[m4 * 4 + 0] = v.x; dv[m4 * 4 + 1] = v.y;
                dv[m4 * 4 + 2] = v.z; dv[m4 * 4 + 3] = v.w;
            }
            float dmin = 3.4e38f; int kmin = 1 << 30;
            #pragma unroll
            for (int i = 0; i < 32; i++) {
                int k = 4 * lane + 128 * (i >> 2) + (i & 3);
                float dd = dv[i];
                if (dd < dmin || (dd == dmin && k < kmin)) { dmin = dd; kmin = k; }
            }
            #pragma unroll
            for (int off = 16; off; off >>= 1) {
                float od = __shfl_xor_sync(0xffffffffu, dmin, off);
                int   ok = __shfl_xor_sync(0xffffffffu, kmin, off);
                if (od < dmin || (od == dmin && ok < kmin)) { dmin = od; kmin = ok; }
            }
            float e[32]; float Z = 0.0f;
            #pragma unroll
            for (int i = 0; i < 32; i++) {
                e[i] = __expf((dmin - dv[i]) * 0.5f);
                Z += e[i];
            }
            #pragma unroll
            for (int off = 16; off; off >>= 1)
                Z += __shfl_xor_sync(0xffffffffu, Z, off);
            float rZ = 1.0f / Z;

            int n = nb + w;
            float4* gq4 = (float4*)(out + O_Q + ((size_t)n * 8 + c) * 1024);
            float ne = 0.0f, qd = 0.0f;
            #pragma unroll
            for (int m4 = 0; m4 < 8; m4++) {
                float4 qv;
                qv.x = e[m4 * 4 + 0] * rZ; qv.y = e[m4 * 4 + 1] * rZ;
                qv.z = e[m4 * 4 + 2] * rZ; qv.w = e[m4 * 4 + 3] * rZ;
                ne += qv.x * __logf(qv.x + 1e-8f) + qv.y * __logf(qv.y + 1e-8f)
                    + qv.z * __logf(qv.z + 1e-8f) + qv.w * __logf(qv.w + 1e-8f);
                qd += qv.x * dv[m4 * 4 + 0] + qv.y * dv[m4 * 4 + 1]
                    + qv.z * dv[m4 * 4 + 2] + qv.w * dv[m4 * 4 + 3];
                gq4[lane + 32 * m4]   = qv;
                row4w[lane + 32 * m4] = qv;   // q back to smem for zq / qbar
            }
            #pragma unroll
            for (int off = 16; off; off >>= 1) {
                ne += __shfl_xor_sync(0xffffffffu, ne, off);
                qd += __shfl_xor_sync(0xffffffffu, qd, off);
            }
            if (lane == 0) { acc_ne += ne; acc_qd += qd; idxs[w] = kmin; }
        }
        __syncthreads();

        // ---- post phase: zq partials, qbar, quantized + indices ----
        {
            float zqp[8];
            #pragma unroll
            for (int n = 0; n < 8; n++) zqp[n] = 0.0f;
            const float4* q4 = (const float4*)ds;
            #pragma unroll 4
            for (int k4 = 0; k4 < 32; k4++) {
                int kb = w * 128 + k4 * 4;
                float c0 = cb_s[(kb + 0) * CB_STRIDE + lane];
                float c1 = cb_s[(kb + 1) * CB_STRIDE + lane];
                float c2 = cb_s[(kb + 2) * CB_STRIDE + lane];
                float c3 = cb_s[(kb + 3) * CB_STRIDE + lane];
                #pragma unroll
                for (int n = 0; n < 8; n++) {
                    float4 qv = q4[n * 256 + w * 32 + k4];
                    zqp[n] = fmaf(qv.x, c0, zqp[n]);
                    zqp[n] = fmaf(qv.y, c1, zqp[n]);
                    zqp[n] = fmaf(qv.z, c2, zqp[n]);
                    zqp[n] = fmaf(qv.w, c3, zqp[n]);
                }
            }
            #pragma unroll
            for (int n = 0; n < 8; n++) red[w * 256 + n * 32 + lane] = zqp[n];

            #pragma unroll
            for (int m = 0; m < 4; m++) {
                int k = t + 256 * m;
                float s = 0.0f;
                #pragma unroll
                for (int n = 0; n < 8; n++) s += ds[n * 1024 + k];
                qba[k] += s;
            }
            {
                int j = t >> 3, ni = t & 7;
                int n = nb + ni;
                int b = n >> 10;
                int kq = idxs[ni];
                out[(size_t)(b * 256 + c * 32 + j) * 1024 + (n & 1023)] =
                    cb_s[kq * CB_STRIDE + j];
            }
            if (t < 8) {
                int n = nb + t;
                int b = n >> 10;
                out[O_IDX + (size_t)b * 8192 + c * 1024 + (n & 1023)] =
                    (float)idxs[t];
            }
        }
        __syncthreads();

        // ---- commitment: reduce zq partials across warps ----
        {
            int n = t >> 5, j = t & 31;
            float s = 0.0f;
            #pragma unroll
            for (int ww = 0; ww < 8; ww++) s += red[ww * 256 + n * 32 + j];
            float diff = zf[n * 32 + j] - s;
            ct_comm = fmaf(diff, diff, ct_comm);
        }
        __syncthreads();
    }

    // ---- block-level flush of accumulators ----
    #pragma unroll
    for (int off = 16; off; off >>= 1)
        ct_comm += __shfl_xor_sync(0xffffffffu, ct_comm, off);
    if (lane == 0) scr[w] = ct_comm;
    __syncthreads();
    if (t == 0) {
        float s = 0.0f;
        #pragma unroll
        for (int i = 0; i < 8; i++) s += scr[i];
        atomicAdd(&g_comm, s);
    }
    if (lane == 0) { atomicAdd(&g_ne, acc_ne); atomicAdd(&g_qd, acc_qd); }
    #pragma unroll
    for (int m = 0; m < 4; m++)
        atomicAdd(&g_qbar[c * 1024 + t + 256 * m], qba[t + 256 * m]);
}

__global__ void lgq_finalize(float* __restrict__ out)
{
    __shared__ float sred[8];
    int t = threadIdx.x, lane = t & 31, w = t >> 5;
    float local = 0.0f;
    for (int i = t; i < CC * KK; i += THREADS) {
        float qb = g_qbar[i] * (1.0f / 4096.0f);
        local += qb * __logf(qb * 1024.0f + 1e-8f);
    }
    #pragma unroll
    for (int off = 16; off; off >>= 1)
        local += __shfl_xor_sync(0xffffffffu, local, off);
    if (lane == 0) sred[w] = local;
    __syncthreads();
    if (t == 0) {
        float s = 0.0f;
        #pragma unroll
        for (int i = 0; i < 8; i++) s += sred[i];
        float balance = s * 0.125f;
        float comm = g_comm * (1.0f / 1048576.0f);
        float mne  = g_ne   * (1.0f / 32768.0f);
        float mqd  = g_qd   * (1.0f / 32768.0f);
        out[O_SC + 0] = comm;
        out[O_SC + 1] = mqd * 0.5f + mne + 6.9314718f;  // + log(1024)
        out[O_SC + 2] = -mne;
        out[O_SC + 3] = balance;
        out[O_SC + 4] = 1.0f;                            // tau
    }
}

extern "C" void kernel_launch(void* const* d_in, const int* in_sizes, int n_in,
                              void* d_out, int out_size)
{
    const float* z   = (const float*)d_in[0];   // (4,256,32,32) f32
    const float* cbg = (const float*)d_in[1];   // (8,1024,32)  f32
    float* out = (float*)d_out;

    cudaFuncSetAttribute(lgq_main, cudaFuncAttributeMaxDynamicSharedMemorySize,
                         SMEM_BYTES);

    lgq_zero<<<32, 256>>>();
    lgq_main<<<dim3(74, 8), THREADS, SMEM_BYTES>>>(z, cbg, out);
    lgq_finalize<<<1, THREADS>>>(out);
}

// round 3
// speedup vs baseline: 1.1507x; 1.1507x over previous
#include <cuda_runtime.h>

typedef unsigned long long u64;

// ---------------- problem constants ----------------
#define CC 8
#define KK 1024
#define NN 4096
#define GX 74
#define TILES 512          // NN / 8
#define THREADS 256

// ---------------- smem layout (float offsets) ----------------
#define OFF_CB   0            // 32768 floats, 1024 rows x 128B, SW128-swizzled
#define OFF_DS   32768        // 8192: [8 n][1024 k] dists (r = cbsq-2cross), then q
#define OFF_ZFT  40960        // 512:  2 x [32 j][8 n]  (double-buffered)
#define OFF_RED  41472        // 4096: 2 x [8 w][8 n][32 j]
#define OFF_QBA  45568        // 1024
#define OFF_SCR  46592        // 16
#define OFF_IDX  46608        // 8 ints + flag
#define SMEM_FLOATS 46620
#define SMEM_BYTES (SMEM_FLOATS * 4)   // 186480 B

// ---------------- output packing (float32, tuple order) ----------------
#define O_IDX   1048576u
#define O_Q     1081344u
#define O_SC    34635776u

// ---------------- global scratch ----------------
__device__ float g_qbar[CC * KK];
__device__ float g_comm;
__device__ float g_ne;
__device__ float g_qd;
__device__ unsigned int g_count;

// ---------------- f32x2 helpers ----------------
__device__ __forceinline__ void fma2(u64 &d, u64 a, u64 b) {
    asm("fma.rn.f32x2 %0, %1, %2, %0;" : "+l"(d) : "l"(a), "l"(b));
}
__device__ __forceinline__ u64 dup2(float x) {
    u64 r; asm("mov.b64 %0, {%1, %1};" : "=l"(r) : "f"(x)); return r;
}
__device__ __forceinline__ u64 pk2(float lo, float hi) {
    u64 r; asm("mov.b64 %0, {%1, %2};" : "=l"(r) : "f"(lo), "f"(hi)); return r;
}
__device__ __forceinline__ void unpk2(u64 v, float &lo, float &hi) {
    asm("mov.b64 {%0, %1}, %2;" : "=f"(lo), "=f"(hi) : "l"(v));
}

// ---------------- swizzled codebook addressing (128B rows, SW128) ----------
__device__ __forceinline__ const float4* cb_vec(const char* cbb, int k, int j4) {
    return (const float4*)(cbb + k * 128 + ((j4 * 16) ^ ((k & 7) << 4)));
}
__device__ __forceinline__ float cb_el(const char* cbb, int k, int j) {
    return *(const float*)(cbb + k * 128 + ((j * 4) ^ ((k & 7) << 4)));
}

__global__ void __launch_bounds__(THREADS, 1)
lgq_main(const float* __restrict__ z, const float* __restrict__ cbg,
         float* __restrict__ out)
{
    extern __shared__ float sm[];
    char*  cbb  = (char*)sm;            // swizzled codebook bytes
    float* ds   = sm + OFF_DS;
    float* zft  = sm + OFF_ZFT;
    float* red  = sm + OFF_RED;
    float* qba  = sm + OFF_QBA;
    float* scr  = sm + OFF_SCR;
    int*   idxs = (int*)(sm + OFF_IDX);

    const int t    = threadIdx.x;
    const int w    = t >> 5;
    const int lane = t & 31;
    const int c    = blockIdx.y;
    const int bx   = blockIdx.x;
    const int jj   = t >> 3;       // staging: j index
    const int ni   = t & 7;        // staging: n-within-tile

    // ---- stage codebook c swizzled + zero qba + stage zf tile0 ----
    {
        const float4* cb4 = (const float4*)(cbg + (size_t)c * (KK * 32));
        for (int i = t; i < KK * 8; i += THREADS) {
            float4 v = cb4[i];
            int k = i >> 3, j4 = i & 7;
            *(float4*)(cbb + k * 128 + ((j4 * 16) ^ ((k & 7) << 4))) = v;
        }
        #pragma unroll
        for (int m = 0; m < 4; m++) qba[t + 256 * m] = 0.0f;
        // tile0 zf
        int n = bx * 8 + ni;
        int b = n >> 10;
        zft[jj * 8 + ni] = z[(size_t)(b * 256 + c * 32 + jj) * 1024 + (n & 1023)];
    }
    __syncthreads();

    // ---- per-thread codeword norms (k = t + 256m), kept in registers ----
    float cq[4];
    #pragma unroll
    for (int m = 0; m < 4; m++) {
        int k = t + 256 * m;
        float s = 0.0f;
        #pragma unroll
        for (int j4 = 0; j4 < 8; j4++) {
            float4 v = *cb_vec(cbb, k, j4);
            s += v.x * v.x + v.y * v.y + v.z * v.z + v.w * v.w;
        }
        cq[m] = s;
    }

    float ct_comm = 0.0f;
    float acc_ne = 0.0f, acc_qd = 0.0f;
    int buf = 0;

    for (int tile = bx; tile < TILES; tile += GX) {
        const int nb = tile * 8;

        // ---- prefetch next tile's zf ----
        const int ntile = tile + GX;
        float zn = 0.0f;
        if (ntile < TILES) {
            int n = ntile * 8 + ni;
            int b = n >> 10;
            zn = z[(size_t)(b * 256 + c * 32 + jj) * 1024 + (n & 1023)];
        }

        // ================= phase 1: distances via f32x2 (n-pairs) =========
        {
            u64 acc[4][4];
            #pragma unroll
            for (int np = 0; np < 4; np++)
                #pragma unroll
                for (int m = 0; m < 4; m++) acc[np][m] = 0ull;

            const ulonglong2* zin = (const ulonglong2*)(zft + buf * 256);
            const int sx = (t & 7) << 4;

            #pragma unroll
            for (int j4 = 0; j4 < 8; j4++) {
                float4 cbv[4];
                const int off = (j4 * 16) ^ sx;
                #pragma unroll
                for (int m = 0; m < 4; m++)
                    cbv[m] = *(const float4*)(cbb + (t + 256 * m) * 128 + off);
                #pragma unroll
                for (int e = 0; e < 4; e++) {
                    int j = j4 * 4 + e;
                    ulonglong2 zA = zin[j * 2];       // pairs (n0,n1),(n2,n3)
                    ulonglong2 zB = zin[j * 2 + 1];   // pairs (n4,n5),(n6,n7)
                    #pragma unroll
                    for (int m = 0; m < 4; m++) {
                        float ce = (e == 0) ? cbv[m].x : (e == 1) ? cbv[m].y
                                 : (e == 2) ? cbv[m].z : cbv[m].w;
                        u64 cd = dup2(ce);
                        fma2(acc[0][m], zA.x, cd);
                        fma2(acc[1][m], zA.y, cd);
                        fma2(acc[2][m], zB.x, cd);
                        fma2(acc[3][m], zB.y, cd);
                    }
                }
            }
            // r = cbsq - 2*cross   (z_sq omitted: cancels in softmax)
            #pragma unroll
            for (int np = 0; np < 4; np++)
                #pragma unroll
                for (int m = 0; m < 4; m++) {
                    float a, b2; unpk2(acc[np][m], a, b2);
                    int k = t + 256 * m;
                    ds[(2 * np) * 1024 + k]     = fmaf(-2.0f, a,  cq[m]);
                    ds[(2 * np + 1) * 1024 + k] = fmaf(-2.0f, b2, cq[m]);
                }
        }
        __syncthreads();

        // ================= phase 2: per-warp softmax / argmin (n = nb+w) ==
        {
            const float4* row4  = (const float4*)(ds + w * 1024);
            float4*       row4w = (float4*)(ds + w * 1024);
            float dv[32];
            #pragma unroll
            for (int m4 = 0; m4 < 8; m4++) {
                float4 v = row4[lane + 32 * m4];
                dv[m4 * 4 + 0] = v.x; dv[m4 * 4 + 1] = v.y;
                dv[m4 * 4 + 2] = v.z; dv[m4 * 4 + 3] = v.w;
            }
            // z_sq for this row (warp-parallel)
            float zz = zft[buf * 256 + lane * 8 + w];
            float zs = zz * zz;
            #pragma unroll
            for (int off = 16; off; off >>= 1)
                zs += __shfl_xor_sync(0xffffffffu, zs, off);

            float rmin = 3.4e38f; int kmin = 1 << 30;
            #pragma unroll
            for (int i = 0; i < 32; i++) {
                int k = 4 * lane + 128 * (i >> 2) + (i & 3);
                float dd = dv[i];
                if (dd < rmin || (dd == rmin && k < kmin)) { rmin = dd; kmin = k; }
            }
            #pragma unroll
            for (int off = 16; off; off >>= 1) {
                float od = __shfl_xor_sync(0xffffffffu, rmin, off);
                int   ok = __shfl_xor_sync(0xffffffffu, kmin, off);
                if (od < rmin || (od == rmin && ok < kmin)) { rmin = od; kmin = ok; }
            }
            float e[32]; float Z = 0.0f;
            #pragma unroll
            for (int i = 0; i < 32; i++) {
                e[i] = __expf((rmin - dv[i]) * 0.5f);
                Z += e[i];
            }
            #pragma unroll
            for (int off = 16; off; off >>= 1)
                Z += __shfl_xor_sync(0xffffffffu, Z, off);
            float rZ = __fdividef(1.0f, Z);

            int n = nb + w;
            float4* gq4 = (float4*)(out + O_Q + ((size_t)n * 8 + c) * 1024);
            float qr = 0.0f;
            #pragma unroll
            for (int m4 = 0; m4 < 8; m4++) {
                float4 qv;
                qv.x = e[m4 * 4 + 0] * rZ; qv.y = e[m4 * 4 + 1] * rZ;
                qv.z = e[m4 * 4 + 2] * rZ; qv.w = e[m4 * 4 + 3] * rZ;
                qr += qv.x * dv[m4 * 4 + 0] + qv.y * dv[m4 * 4 + 1]
                    + qv.z * dv[m4 * 4 + 2] + qv.w * dv[m4 * 4 + 3];
                gq4[lane + 32 * m4]   = qv;
                row4w[lane + 32 * m4] = qv;
            }
            #pragma unroll
            for (int off = 16; off; off >>= 1)
                qr += __shfl_xor_sync(0xffffffffu, qr, off);
            if (lane == 0) {
                // neg-entropy identity: sum q log q = 0.5(rmin - qr) - log Z
                acc_ne += 0.5f * (rmin - qr) - __logf(Z);
                acc_qd += qr + zs;          // sum q*d  (z_sq restored)
                idxs[w] = kmin;
            }
        }
        __syncthreads();

        // ================= phase 3: zq via f32x2 (k-pairs), qbar, outputs =
        {
            u64 zq2[8];
            #pragma unroll
            for (int n = 0; n < 8; n++) zq2[n] = 0ull;

            const ulonglong2* q2 = (const ulonglong2*)ds;
            #pragma unroll 4
            for (int k4 = 0; k4 < 32; k4++) {
                int kb = w * 128 + k4 * 4;
                float c0 = cb_el(cbb, kb + 0, lane);
                float c1 = cb_el(cbb, kb + 1, lane);
                float c2 = cb_el(cbb, kb + 2, lane);
                float c3 = cb_el(cbb, kb + 3, lane);
                u64 c01 = pk2(c0, c1), c23 = pk2(c2, c3);
                #pragma unroll
                for (int n = 0; n < 8; n++) {
                    ulonglong2 qq = q2[n * 256 + w * 32 + k4];
                    fma2(zq2[n], qq.x, c01);
                    fma2(zq2[n], qq.y, c23);
                }
            }
            float* rd = red + buf * 2048;
            #pragma unroll
            for (int n = 0; n < 8; n++) {
                float a, b2; unpk2(zq2[n], a, b2);
                rd[w * 256 + n * 32 + lane] = a + b2;
            }

            // qbar accumulation
            #pragma unroll
            for (int m = 0; m < 4; m++) {
                int k = t + 256 * m;
                float s = 0.0f;
                #pragma unroll
                for (int n = 0; n < 8; n++) s += ds[n * 1024 + k];
                qba[k] += s;
            }
            // quantized (hard codewords) + indices
            {
                int n = nb + ni;
                int b = n >> 10;
                int kq = idxs[ni];
                out[(size_t)(b * 256 + c * 32 + jj) * 1024 + (n & 1023)] =
                    cb_el(cbb, kq, jj);
            }
            if (t < 8) {
                int n = nb + t;
                int b = n >> 10;
                out[O_IDX + (size_t)b * 8192 + c * 1024 + (n & 1023)] =
                    (float)idxs[t];
            }
            // store prefetched zf into other buffer
            if (ntile < TILES) zft[(buf ^ 1) * 256 + jj * 8 + ni] = zn;
        }
        __syncthreads();

        // ================= commitment =====================================
        {
            const float* rd = red + buf * 2048;
            float s = 0.0f;
            #pragma unroll
            for (int ww = 0; ww < 8; ww++) s += rd[ww * 256 + w * 32 + lane];
            float diff = zft[buf * 256 + lane * 8 + w] - s;
            ct_comm = fmaf(diff, diff, ct_comm);
        }
        buf ^= 1;   // red/zft are double-buffered: no barrier needed here
    }

    // ---- flush block accumulators ----
    #pragma unroll
    for (int off = 16; off; off >>= 1)
        ct_comm += __shfl_xor_sync(0xffffffffu, ct_comm, off);
    if (lane == 0) scr[w] = ct_comm;
    __syncthreads();
    if (t == 0) {
        float s = 0.0f;
        #pragma unroll
        for (int i = 0; i < 8; i++) s += scr[i];
        atomicAdd(&g_comm, s);
    }
    if (lane == 0) { atomicAdd(&g_ne, acc_ne); atomicAdd(&g_qd, acc_qd); }
    #pragma unroll
    for (int m = 0; m < 4; m++)
        atomicAdd(&g_qbar[c * 1024 + t + 256 * m], qba[t + 256 * m]);

    // ---- last-block finalize (ticket) ----
    __threadfence();
    int* flag = (int*)(sm + OFF_IDX);
    if (t == 0) {
        unsigned int v = atomicAdd(&g_count, 1u);
        flag[0] = (v == (unsigned)(GX * CC - 1));
    }
    __syncthreads();
    if (flag[0]) {
        float local = 0.0f;
        for (int i = t; i < CC * KK; i += THREADS) {
            float qb = g_qbar[i] * (1.0f / 4096.0f);
            local += qb * __logf(fmaf(qb, 1024.0f, 1e-8f));
            g_qbar[i] = 0.0f;                   // reset for next replay
        }
        #pragma unroll
        for (int off = 16; off; off >>= 1)
            local += __shfl_xor_sync(0xffffffffu, local, off);
        if (lane == 0) scr[w] = local;
        __syncthreads();
        if (t == 0) {
            float s = 0.0f;
            #pragma unroll
            for (int i = 0; i < 8; i++) s += scr[i];
            float balance = s * 0.125f;
            float comm = g_comm * (1.0f / 1048576.0f);
            float mne  = g_ne   * (1.0f / 32768.0f);
            float mqd  = g_qd   * (1.0f / 32768.0f);
            out[O_SC + 0] = comm;
            out[O_SC + 1] = fmaf(mqd, 0.5f, mne) + 6.93147180559945f;
            out[O_SC + 2] = -mne;
            out[O_SC + 3] = balance;
            out[O_SC + 4] = 1.0f;
            g_comm = 0.0f; g_ne = 0.0f; g_qd = 0.0f;   // reset scratch
            g_count = 0u;
        }
    }
}

extern "C" void kernel_launch(void* const* d_in, const int* in_sizes, int n_in,
                              void* d_out, int out_size)
{
    const float* z   = (const float*)d_in[0];   // (4,256,32,32) f32
    const float* cbg = (const float*)d_in[1];   // (8,1024,32)  f32
    float* out = (float*)d_out;

    cudaFuncSetAttribute(lgq_main, cudaFuncAttributeMaxDynamicSharedMemorySize,
                         SMEM_BYTES);
    lgq_main<<<dim3(GX, CC), THREADS, SMEM_BYTES>>>(z, cbg, out);
}

// round 4
// speedup vs baseline: 1.2656x; 1.0999x over previous
#include <cuda_runtime.h>

typedef unsigned long long u64;

// ---------------- problem constants ----------------
#define CC 8
#define KK 1024
#define NT 16
#define TILES 256          // 4096 / NT
#define THREADS 512
#define GX 18              // grid.x -> 144 blocks, single wave

// ---------------- smem layout (float offsets) ----------------
#define OFF_CB   0            // 32768 floats: 1024 rows x 128B, SW128-swizzled
#define OFF_DS   32768        // 16384: [16 n][1024 k]  dists -> e -> q
#define OFF_ZFT  49152        // 1024:  2 x [32 j][16 n]
#define OFF_RED  50176        // 4096:  [8 slab][16 n][32 j]
#define OFF_SCR  54272        // 16
#define OFF_IDX  54288        // 16 ints + flag
#define SMEM_FLOATS 54312
#define SMEM_BYTES (SMEM_FLOATS * 4)   // 217248 B

// ---------------- output packing (float32, tuple order) ----------------
#define O_IDX   1048576u
#define O_Q     1081344u
#define O_SC    34635776u

// ---------------- global scratch ----------------
__device__ float g_qbar[CC * KK];
__device__ float g_comm;
__device__ float g_ne;
__device__ float g_qd;
__device__ unsigned int g_count;

// ---------------- f32x2 helpers ----------------
__device__ __forceinline__ void fma2(u64 &d, u64 a, u64 b) {
    asm("fma.rn.f32x2 %0, %1, %2, %0;" : "+l"(d) : "l"(a), "l"(b));
}
__device__ __forceinline__ u64 dup2(float x) {
    u64 r; asm("mov.b64 %0, {%1, %1};" : "=l"(r) : "f"(x)); return r;
}
__device__ __forceinline__ u64 pk2(float lo, float hi) {
    u64 r; asm("mov.b64 %0, {%1, %2};" : "=l"(r) : "f"(lo), "f"(hi)); return r;
}
__device__ __forceinline__ void unpk2(u64 v, float &lo, float &hi) {
    asm("mov.b64 {%0, %1}, %2;" : "=f"(lo), "=f"(hi) : "l"(v));
}

// ---------------- swizzled codebook addressing (128B rows, SW128) ----------
__device__ __forceinline__ const float4* cb_vec(const char* cbb, int k, int j4) {
    return (const float4*)(cbb + k * 128 + ((j4 * 16) ^ ((k & 7) << 4)));
}
__device__ __forceinline__ float cb_el(const char* cbb, int k, int j) {
    return *(const float*)(cbb + k * 128 + ((j * 4) ^ ((k & 7) << 4)));
}

__global__ void __launch_bounds__(THREADS, 1)
lgq_main(const float* __restrict__ z, const float* __restrict__ cbg,
         float* __restrict__ out)
{
    extern __shared__ float sm[];
    char*  cbb  = (char*)sm;
    float* ds   = sm + OFF_DS;
    float* zft  = sm + OFF_ZFT;
    float* red  = sm + OFF_RED;
    float* scr  = sm + OFF_SCR;
    int*   idxs = (int*)(sm + OFF_IDX);

    const int t    = threadIdx.x;
    const int w    = t >> 5;
    const int lane = t & 31;
    const int c    = blockIdx.y;
    const int bx   = blockIdx.x;
    const int jj   = t >> 4;       // staging: j index (0..31)
    const int ni   = t & 15;       // staging: n-within-tile (0..15)

    float zsq_acc = 0.0f;          // per-thread sum of z^2 over staged elements

    // ---- stage codebook c swizzled + zf tile0 ----
    {
        const float4* cb4 = (const float4*)(cbg + (size_t)c * (KK * 32));
        #pragma unroll
        for (int it = 0; it < 16; it++) {
            int i = t + it * THREADS;
            float4 v = cb4[i];
            int k = i >> 3, j4 = i & 7;
            *(float4*)(cbb + k * 128 + ((j4 * 16) ^ ((k & 7) << 4))) = v;
        }
        int n = bx * NT + ni;
        int b = n >> 10;
        float v = z[(size_t)(b * 256 + c * 32 + jj) * 1024 + (n & 1023)];
        zft[jj * 16 + ni] = v;
        zsq_acc += v * v;
    }
    __syncthreads();

    // ---- codeword norms for k = t, t+512 (registers) ----
    float cq[2];
    #pragma unroll
    for (int m = 0; m < 2; m++) {
        int k = t + 512 * m;
        float s = 0.0f;
        #pragma unroll
        for (int j4 = 0; j4 < 8; j4++) {
            float4 v = *cb_vec(cbb, k, j4);
            s += v.x * v.x + v.y * v.y + v.z * v.z + v.w * v.w;
        }
        cq[m] = s;
    }

    float ct_comm = 0.0f;
    float acc_ne = 0.0f, acc_qd = 0.0f;   // lane0-of-warp accumulators
    float qbr0 = 0.0f, qbr1 = 0.0f;       // qbar partials for k = t, t+512
    int buf = 0;

    for (int tile = bx; tile < TILES; tile += GX) {
        const int nb = tile * NT;

        // ---- prefetch next tile's zf ----
        const int ntile = tile + GX;
        float zn = 0.0f;
        if (ntile < TILES) {
            int n = ntile * NT + ni;
            int b = n >> 10;
            zn = z[(size_t)(b * 256 + c * 32 + jj) * 1024 + (n & 1023)];
        }

        // ================= phase 1: r = cbsq - 2*cross via f32x2 ==========
        {
            u64 acc[8][2];
            #pragma unroll
            for (int np = 0; np < 8; np++) { acc[np][0] = 0ull; acc[np][1] = 0ull; }

            const int sx = (t & 7) << 4;
            const float* zb = zft + buf * 512;

            #pragma unroll
            for (int j4 = 0; j4 < 8; j4++) {
                const int off = (j4 * 16) ^ sx;
                float4 cv0 = *(const float4*)(cbb + t * 128 + off);
                float4 cv1 = *(const float4*)(cbb + (t + 512) * 128 + off);
                #pragma unroll
                for (int e = 0; e < 4; e++) {
                    int j = j4 * 4 + e;
                    const ulonglong2* zp = (const ulonglong2*)(zb + j * 16);
                    ulonglong2 zA = zp[0], zB = zp[1];  // n 0..7
                    ulonglong2 zC = zp[2], zD = zp[3];  // n 8..15
                    float e0 = (e == 0) ? cv0.x : (e == 1) ? cv0.y
                             : (e == 2) ? cv0.z : cv0.w;
                    float e1 = (e == 0) ? cv1.x : (e == 1) ? cv1.y
                             : (e == 2) ? cv1.z : cv1.w;
                    u64 d0 = dup2(e0), d1 = dup2(e1);
                    fma2(acc[0][0], zA.x, d0); fma2(acc[0][1], zA.x, d1);
                    fma2(acc[1][0], zA.y, d0); fma2(acc[1][1], zA.y, d1);
                    fma2(acc[2][0], zB.x, d0); fma2(acc[2][1], zB.x, d1);
                    fma2(acc[3][0], zB.y, d0); fma2(acc[3][1], zB.y, d1);
                    fma2(acc[4][0], zC.x, d0); fma2(acc[4][1], zC.x, d1);
                    fma2(acc[5][0], zC.y, d0); fma2(acc[5][1], zC.y, d1);
                    fma2(acc[6][0], zD.x, d0); fma2(acc[6][1], zD.x, d1);
                    fma2(acc[7][0], zD.y, d0); fma2(acc[7][1], zD.y, d1);
                }
            }
            #pragma unroll
            for (int np = 0; np < 8; np++)
                #pragma unroll
                for (int m = 0; m < 2; m++) {
                    float a, b2; unpk2(acc[np][m], a, b2);
                    int k = t + 512 * m;
                    ds[(2 * np) * 1024 + k]     = fmaf(-2.0f, a,  cq[m]);
                    ds[(2 * np + 1) * 1024 + k] = fmaf(-2.0f, b2, cq[m]);
                }
        }
        __syncthreads();

        // ================= phase 2: softmax / argmin, warp w <-> n = w ====
        {
            float* row = ds + w * 1024;
            const float4* row4  = (const float4*)row;
            float4*       row4w = (float4*)row;
            float dv[32];
            #pragma unroll
            for (int m4 = 0; m4 < 8; m4++) {
                float4 v = row4[lane + 32 * m4];
                dv[m4 * 4 + 0] = v.x; dv[m4 * 4 + 1] = v.y;
                dv[m4 * 4 + 2] = v.z; dv[m4 * 4 + 3] = v.w;
            }
            float rmin = 3.4e38f; int kmin = 1 << 30;
            #pragma unroll
            for (int i = 0; i < 32; i++) {
                int k = 4 * lane + 128 * (i >> 2) + (i & 3);
                float dd = dv[i];
                if (dd < rmin || (dd == rmin && k < kmin)) { rmin = dd; kmin = k; }
            }
            #pragma unroll
            for (int off = 16; off; off >>= 1) {
                float od = __shfl_xor_sync(0xffffffffu, rmin, off);
                int   ok = __shfl_xor_sync(0xffffffffu, kmin, off);
                if (od < rmin || (od == rmin && ok < kmin)) { rmin = od; kmin = ok; }
            }
            // pass 1: e = exp((rmin-d)/2); accumulate Z, sum(e*d); stash e in ds
            float Z = 0.0f, sed = 0.0f;
            #pragma unroll
            for (int m4 = 0; m4 < 8; m4++) {
                float4 ev;
                ev.x = __expf((rmin - dv[m4 * 4 + 0]) * 0.5f);
                ev.y = __expf((rmin - dv[m4 * 4 + 1]) * 0.5f);
                ev.z = __expf((rmin - dv[m4 * 4 + 2]) * 0.5f);
                ev.w = __expf((rmin - dv[m4 * 4 + 3]) * 0.5f);
                Z   += ev.x + ev.y + ev.z + ev.w;
                sed += ev.x * dv[m4 * 4 + 0] + ev.y * dv[m4 * 4 + 1]
                     + ev.z * dv[m4 * 4 + 2] + ev.w * dv[m4 * 4 + 3];
                row4w[lane + 32 * m4] = ev;
            }
            #pragma unroll
            for (int off = 16; off; off >>= 1) {
                Z   += __shfl_xor_sync(0xffffffffu, Z, off);
                sed += __shfl_xor_sync(0xffffffffu, sed, off);
            }
            float rZ = __fdividef(1.0f, Z);
            float qd = sed * rZ;

            // pass 2: q = e * rZ -> ds + global
            int n = nb + w;
            float4* gq4 = (float4*)(out + O_Q + ((size_t)n * 8 + c) * 1024);
            #pragma unroll
            for (int m4 = 0; m4 < 8; m4++) {
                float4 ev = row4[lane + 32 * m4];
                ev.x *= rZ; ev.y *= rZ; ev.z *= rZ; ev.w *= rZ;
                row4w[lane + 32 * m4] = ev;
                gq4[lane + 32 * m4]   = ev;
            }
            if (lane == 0) {
                acc_ne += 0.5f * (rmin - qd) - __logf(Z);
                acc_qd += qd;
                idxs[w] = kmin;
            }
        }
        __syncthreads();

        // ================= phase 3: zq (f32x2 k-pairs), qbar, outputs =====
        {
            const int s  = w & 7;          // k slab [s*128, s*128+128)
            const int nh = (w >> 3) * 8;   // n half
            u64 zq2[8];
            #pragma unroll
            for (int n2 = 0; n2 < 8; n2++) zq2[n2] = 0ull;

            #pragma unroll 4
            for (int k4 = 0; k4 < 32; k4++) {
                int kb = s * 128 + k4 * 4;
                float c0 = cb_el(cbb, kb + 0, lane);
                float c1 = cb_el(cbb, kb + 1, lane);
                float c2 = cb_el(cbb, kb + 2, lane);
                float c3 = cb_el(cbb, kb + 3, lane);
                u64 c01 = pk2(c0, c1), c23 = pk2(c2, c3);
                #pragma unroll
                for (int n2 = 0; n2 < 8; n2++) {
                    ulonglong2 qq = *(const ulonglong2*)(ds + (nh + n2) * 1024 + kb);
                    fma2(zq2[n2], qq.x, c01);
                    fma2(zq2[n2], qq.y, c23);
                }
            }
            #pragma unroll
            for (int n2 = 0; n2 < 8; n2++) {
                float a, b2; unpk2(zq2[n2], a, b2);
                red[s * 512 + (nh + n2) * 32 + lane] = a + b2;
            }

            // qbar partials (k = t, t+512) straight from q rows
            float s0 = 0.0f, s1 = 0.0f;
            #pragma unroll
            for (int n2 = 0; n2 < 16; n2++) {
                s0 += ds[n2 * 1024 + t];
                s1 += ds[n2 * 1024 + t + 512];
            }
            qbr0 += s0; qbr1 += s1;

            // quantized (hard codewords) + indices
            {
                int n = nb + ni;
                int b = n >> 10;
                int kq = idxs[ni];
                out[(size_t)(b * 256 + c * 32 + jj) * 1024 + (n & 1023)] =
                    cb_el(cbb, kq, jj);
            }
            if (t < 16) {
                int n = nb + t;
                int b = n >> 10;
                out[O_IDX + (size_t)b * 8192 + c * 1024 + (n & 1023)] =
                    (float)idxs[t];
            }
            if (ntile < TILES) {
                zft[(buf ^ 1) * 512 + jj * 16 + ni] = zn;
                zsq_acc += zn * zn;
            }
        }
        __syncthreads();

        // ================= commitment: t <-> (n = w, j = lane) ============
        {
            float s = 0.0f;
            #pragma unroll
            for (int ss = 0; ss < 8; ss++) s += red[ss * 512 + w * 32 + lane];
            float diff = zft[buf * 512 + lane * 16 + w] - s;
            ct_comm = fmaf(diff, diff, ct_comm);
        }
        buf ^= 1;   // safe: 2 barriers separate this read from the next red write
    }

    // ---- flush accumulators ----
    #pragma unroll
    for (int off = 16; off; off >>= 1) {
        ct_comm += __shfl_xor_sync(0xffffffffu, ct_comm, off);
        zsq_acc += __shfl_xor_sync(0xffffffffu, zsq_acc, off);
    }
    if (lane == 0) {
        atomicAdd(&g_comm, ct_comm);
        atomicAdd(&g_ne, acc_ne);
        atomicAdd(&g_qd, acc_qd + zsq_acc);
    }
    atomicAdd(&g_qbar[c * 1024 + t], qbr0);
    atomicAdd(&g_qbar[c * 1024 + t + 512], qbr1);

    // ---- last-block finalize (ticket) ----
    __threadfence();
    int* flag = (int*)(sm + OFF_IDX);
    if (t == 0) {
        unsigned int v = atomicAdd(&g_count, 1u);
        flag[16] = (v == (unsigned)(GX * CC - 1));
    }
    __syncthreads();
    if (flag[16]) {
        float local = 0.0f;
        for (int i = t; i < CC * KK; i += THREADS) {
            float qb = g_qbar[i] * (1.0f / 4096.0f);
            local += qb * __logf(fmaf(qb, 1024.0f, 1e-8f));
            g_qbar[i] = 0.0f;                   // reset for next graph replay
        }
        #pragma unroll
        for (int off = 16; off; off >>= 1)
            local += __shfl_xor_sync(0xffffffffu, local, off);
        if (lane == 0) scr[w] = local;
        __syncthreads();
        if (t == 0) {
            float s = 0.0f;
            #pragma unroll
            for (int i = 0; i < 16; i++) s += scr[i];
            float balance = s * 0.125f;
            float comm = g_comm * (1.0f / 1048576.0f);
            float mne  = g_ne   * (1.0f / 32768.0f);
            float mqd  = g_qd   * (1.0f / 32768.0f);
            out[O_SC + 0] = comm;
            out[O_SC + 1] = fmaf(mqd, 0.5f, mne) + 6.93147180559945f;
            out[O_SC + 2] = -mne;
            out[O_SC + 3] = balance;
            out[O_SC + 4] = 1.0f;
            g_comm = 0.0f; g_ne = 0.0f; g_qd = 0.0f;
            g_count = 0u;
        }
    }
}

extern "C" void kernel_launch(void* const* d_in, const int* in_sizes, int n_in,
                              void* d_out, int out_size)
{
    const float* z   = (const float*)d_in[0];   // (4,256,32,32) f32
    const float* cbg = (const float*)d_in[1];   // (8,1024,32)  f32
    float* out = (float*)d_out;

    cudaFuncSetAttribute(lgq_main, cudaFuncAttributeMaxDynamicSharedMemorySize,
                         SMEM_BYTES);
    lgq_main<<<dim3(GX, CC), THREADS, SMEM_BYTES>>>(z, cbg, out);
}

// round 6
// speedup vs baseline: 1.3282x; 1.0494x over previous
#include <cuda_runtime.h>

typedef unsigned long long u64;

// ---------------- problem constants ----------------
#define CC 8
#define KK 1024
#define NT 16
#define TILES 256              // 4096 / NT
#define THREADS 512
#define NBLOCKS 148            // one block per SM, contiguous task ranges

// ---------------- smem layout (float offsets) ----------------
#define OFF_CB   0             // 32768: 1024 rows x 128B, SW128-swizzled
#define OFF_DS   32768         // 16384: [16 n][1024 k]  dists -> q
#define OFF_ZFT  49152         // 1024:  2 x [32 j][16 n]
#define OFF_ZFTT 50176         // 1056:  2 x [16 n][stride 33 j]  (transposed)
#define OFF_RED  51232         // 4096:  [8 slab][16 n][32 j]  (SINGLE buffer)
#define OFF_SCR  55328         // 16
#define OFF_IDX  55344         // 24 ints
#define SMEM_FLOATS 55368
#define SMEM_BYTES (SMEM_FLOATS * 4)   // 221472 B

// ---------------- output packing (float32, tuple order) ----------------
#define O_IDX   1048576u
#define O_Q     1081344u
#define O_SC    34635776u

// ---------------- global scratch ----------------
__device__ float g_qbar[CC * KK];
__device__ float g_comm;
__device__ float g_ne;
__device__ float g_qd;
__device__ unsigned int g_count;

// ---------------- f32x2 helpers ----------------
__device__ __forceinline__ void fma2(u64 &d, u64 a, u64 b) {
    asm("fma.rn.f32x2 %0, %1, %2, %0;" : "+l"(d) : "l"(a), "l"(b));
}
__device__ __forceinline__ u64 dup2(float x) {
    u64 r; asm("mov.b64 %0, {%1, %1};" : "=l"(r) : "f"(x)); return r;
}
__device__ __forceinline__ u64 pk2(float lo, float hi) {
    u64 r; asm("mov.b64 %0, {%1, %2};" : "=l"(r) : "f"(lo), "f"(hi)); return r;
}
__device__ __forceinline__ void unpk2(u64 v, float &lo, float &hi) {
    asm("mov.b64 {%0, %1}, %2;" : "=f"(lo), "=f"(hi) : "l"(v));
}

// ---------------- swizzled codebook addressing (128B rows, SW128) ----------
__device__ __forceinline__ const float4* cb_vec(const char* cbb, int k, int j4) {
    return (const float4*)(cbb + k * 128 + ((j4 * 16) ^ ((k & 7) << 4)));
}
__device__ __forceinline__ float cb_el(const char* cbb, int k, int j) {
    return *(const float*)(cbb + k * 128 + ((j * 4) ^ ((k & 7) << 4)));
}

__global__ void __launch_bounds__(THREADS, 1)
lgq_main(const float* __restrict__ z, const float* __restrict__ cbg,
         float* __restrict__ out)
{
    extern __shared__ float sm[];
    char*  cbb  = (char*)sm;
    float* ds   = sm + OFF_DS;
    float* zft  = sm + OFF_ZFT;
    float* zftT = sm + OFF_ZFTT;
    float* red  = sm + OFF_RED;
    float* scr  = sm + OFF_SCR;
    int*   idxs = (int*)(sm + OFF_IDX);

    const int t    = threadIdx.x;
    const int w    = t >> 5;
    const int lane = t & 31;
    const int bx   = blockIdx.x;
    const int jj   = t >> 4;       // staging j (0..31)
    const int ni   = t & 15;       // staging n-within-tile (0..15)

    // ---- contiguous task range: task = (c << 8) | tile ----
    const int start = bx * 13 + min(bx, 124);
    const int gend  = start + 13 + (bx < 124 ? 1 : 0);
    int c = start >> 8;

    float zsq_acc = 0.0f;

    // ---- stage codebook c (swizzled) + zf of first tile ----
    {
        const float4* cb4 = (const float4*)(cbg + (size_t)c * (KK * 32));
        #pragma unroll
        for (int it = 0; it < 16; it++) {
            int i = t + it * THREADS;
            float4 v = cb4[i];
            int k = i >> 3, j4 = i & 7;
            *(float4*)(cbb + k * 128 + ((j4 * 16) ^ ((k & 7) << 4))) = v;
        }
        int n = (start & 255) * NT + ni;
        int b = n >> 10;
        float v = z[(size_t)(b * 256 + c * 32 + jj) * 1024 + (n & 1023)];
        zft[jj * 16 + ni]  = v;
        zftT[ni * 33 + jj] = v;
        zsq_acc += v * v;
    }
    __syncthreads();

    // ---- codeword norms for k = t, t+512 ----
    float cq[2];
    #pragma unroll
    for (int m = 0; m < 2; m++) {
        int k = t + 512 * m;
        float s = 0.0f;
        #pragma unroll
        for (int j4 = 0; j4 < 8; j4++) {
            float4 v = *cb_vec(cbb, k, j4);
            s += v.x * v.x + v.y * v.y + v.z * v.z + v.w * v.w;
        }
        cq[m] = s;
    }

    float ct_comm = 0.0f;
    float acc_ne = 0.0f, acc_qd = 0.0f;
    float qbr0 = 0.0f, qbr1 = 0.0f;
    int buf = 0;

    for (int gi = start; gi < gend; gi++) {
        const int nb = (gi & 255) * NT;

        // ---- prefetch next task's zf (may be a different c) ----
        const int gn = gi + 1;
        const bool has_next = (gn < gend);
        const int nc = gn >> 8;
        float zn = 0.0f;
        if (has_next) {
            int n = (gn & 255) * NT + ni;
            int b = n >> 10;
            zn = z[(size_t)(b * 256 + nc * 32 + jj) * 1024 + (n & 1023)];
        }

        // ================= phase 1: r = cbsq - 2*cross via f32x2 ==========
        {
            u64 acc[8][2];
            #pragma unroll
            for (int np = 0; np < 8; np++) { acc[np][0] = 0ull; acc[np][1] = 0ull; }

            const int sx = (t & 7) << 4;
            const float* zb = zft + buf * 512;

            #pragma unroll
            for (int j4 = 0; j4 < 8; j4++) {
                const int off = (j4 * 16) ^ sx;
                float4 cv0 = *(const float4*)(cbb + t * 128 + off);
                float4 cv1 = *(const float4*)(cbb + (t + 512) * 128 + off);
                #pragma unroll
                for (int e = 0; e < 4; e++) {
                    int j = j4 * 4 + e;
                    const ulonglong2* zp = (const ulonglong2*)(zb + j * 16);
                    ulonglong2 zA = zp[0], zB = zp[1];
                    ulonglong2 zC = zp[2], zD = zp[3];
                    float e0 = (e == 0) ? cv0.x : (e == 1) ? cv0.y
                             : (e == 2) ? cv0.z : cv0.w;
                    float e1 = (e == 0) ? cv1.x : (e == 1) ? cv1.y
                             : (e == 2) ? cv1.z : cv1.w;
                    u64 d0 = dup2(e0), d1 = dup2(e1);
                    fma2(acc[0][0], zA.x, d0); fma2(acc[0][1], zA.x, d1);
                    fma2(acc[1][0], zA.y, d0); fma2(acc[1][1], zA.y, d1);
                    fma2(acc[2][0], zB.x, d0); fma2(acc[2][1], zB.x, d1);
                    fma2(acc[3][0], zB.y, d0); fma2(acc[3][1], zB.y, d1);
                    fma2(acc[4][0], zC.x, d0); fma2(acc[4][1], zC.x, d1);
                    fma2(acc[5][0], zC.y, d0); fma2(acc[5][1], zC.y, d1);
                    fma2(acc[6][0], zD.x, d0); fma2(acc[6][1], zD.x, d1);
                    fma2(acc[7][0], zD.y, d0); fma2(acc[7][1], zD.y, d1);
                }
            }
            #pragma unroll
            for (int np = 0; np < 8; np++)
                #pragma unroll
                for (int m = 0; m < 2; m++) {
                    float a, b2; unpk2(acc[np][m], a, b2);
                    int k = t + 512 * m;
                    ds[(2 * np) * 1024 + k]     = fmaf(-2.0f, a,  cq[m]);
                    ds[(2 * np + 1) * 1024 + k] = fmaf(-2.0f, b2, cq[m]);
                }
        }
        __syncthreads();

        // ========== phase 2: single-pass softmax / argmin (n = nb + w) ====
        {
            float* row = ds + w * 1024;
            const float4* row4  = (const float4*)row;
            float4*       row4w = (float4*)row;
            float dv[32];
            #pragma unroll
            for (int m4 = 0; m4 < 8; m4++) {
                float4 v = row4[lane + 32 * m4];
                dv[m4 * 4 + 0] = v.x; dv[m4 * 4 + 1] = v.y;
                dv[m4 * 4 + 2] = v.z; dv[m4 * 4 + 3] = v.w;
            }
            float rmin = 3.4e38f; int kmin = 1 << 30;
            #pragma unroll
            for (int i = 0; i < 32; i++) {
                int k = 4 * lane + 128 * (i >> 2) + (i & 3);
                float dd = dv[i];
                if (dd < rmin || (dd == rmin && k < kmin)) { rmin = dd; kmin = k; }
            }
            #pragma unroll
            for (int off = 16; off; off >>= 1) {
                float od = __shfl_xor_sync(0xffffffffu, rmin, off);
                int   ok = __shfl_xor_sync(0xffffffffu, kmin, off);
                if (od < rmin || (od == rmin && ok < kmin)) { rmin = od; kmin = ok; }
            }
            // e = exp((rmin-d)/2), kept in dv[] (no smem round trip)
            float Z = 0.0f, sed = 0.0f;
            #pragma unroll
            for (int i = 0; i < 32; i++) {
                float told = dv[i];
                float ev = __expf((rmin - told) * 0.5f);
                Z += ev;
                sed = fmaf(ev, told, sed);
                dv[i] = ev;
            }
            #pragma unroll
            for (int off = 16; off; off >>= 1) {
                Z   += __shfl_xor_sync(0xffffffffu, Z, off);
                sed += __shfl_xor_sync(0xffffffffu, sed, off);
            }
            float rZ = __fdividef(1.0f, Z);
            float qd = sed * rZ;

            int n = nb + w;
            float4* gq4 = (float4*)(out + O_Q + ((size_t)n * 8 + c) * 1024);
            #pragma unroll
            for (int m4 = 0; m4 < 8; m4++) {
                float4 qv;
                qv.x = dv[m4 * 4 + 0] * rZ; qv.y = dv[m4 * 4 + 1] * rZ;
                qv.z = dv[m4 * 4 + 2] * rZ; qv.w = dv[m4 * 4 + 3] * rZ;
                row4w[lane + 32 * m4] = qv;   // q -> smem for phase 3
                gq4[lane + 32 * m4]   = qv;   // q -> global
            }
            if (lane == 0) {
                acc_ne += 0.5f * (rmin - qd) - __logf(Z);
                acc_qd += qd;
                idxs[w] = kmin;
            }
        }
        __syncthreads();

        // ========== phase 3: zq (f32x2 k-pairs), qbar, outputs ============
        {
            const int s  = w & 7;
            const int nh = (w >> 3) * 8;
            u64 zq2[8];
            #pragma unroll
            for (int n2 = 0; n2 < 8; n2++) zq2[n2] = 0ull;

            #pragma unroll 4
            for (int k4 = 0; k4 < 32; k4++) {
                int kb = s * 128 + k4 * 4;
                float c0 = cb_el(cbb, kb + 0, lane);
                float c1 = cb_el(cbb, kb + 1, lane);
                float c2 = cb_el(cbb, kb + 2, lane);
                float c3 = cb_el(cbb, kb + 3, lane);
                u64 c01 = pk2(c0, c1), c23 = pk2(c2, c3);
                #pragma unroll
                for (int n2 = 0; n2 < 8; n2++) {
                    ulonglong2 qq = *(const ulonglong2*)(ds + (nh + n2) * 1024 + kb);
                    fma2(zq2[n2], qq.x, c01);
                    fma2(zq2[n2], qq.y, c23);
                }
            }
            // single-buffered red: safe — the commitment read of this tile
            // precedes the next phase-3 write by two full __syncthreads.
            #pragma unroll
            for (int n2 = 0; n2 < 8; n2++) {
                float a, b2; unpk2(zq2[n2], a, b2);
                red[s * 512 + (nh + n2) * 32 + lane] = a + b2;
            }

            float s0 = 0.0f, s1 = 0.0f;
            #pragma unroll
            for (int n2 = 0; n2 < 16; n2++) {
                s0 += ds[n2 * 1024 + t];
                s1 += ds[n2 * 1024 + t + 512];
            }
            qbr0 += s0; qbr1 += s1;

            {
                int n = nb + ni;
                int b = n >> 10;
                int kq = idxs[ni];
                out[(size_t)(b * 256 + c * 32 + jj) * 1024 + (n & 1023)] =
                    cb_el(cbb, kq, jj);
            }
            if (t < 16) {
                int n = nb + t;
                int b = n >> 10;
                out[O_IDX + (size_t)b * 8192 + c * 1024 + (n & 1023)] =
                    (float)idxs[t];
            }
            if (has_next) {
                zft[(buf ^ 1) * 512 + jj * 16 + ni]  = zn;
                zftT[(buf ^ 1) * 528 + ni * 33 + jj] = zn;
                zsq_acc += zn * zn;
            }
        }
        __syncthreads();

        // ========== commitment: t <-> (n = w, j = lane), conflict-free ====
        {
            float s = 0.0f;
            #pragma unroll
            for (int ss = 0; ss < 8; ss++) s += red[ss * 512 + w * 32 + lane];
            float diff = zftT[buf * 528 + w * 33 + lane] - s;
            ct_comm = fmaf(diff, diff, ct_comm);
        }
        buf ^= 1;

        // ---- codebook switch (at most once per block) ----
        if (has_next && nc != c) {
            atomicAdd(&g_qbar[c * 1024 + t],       qbr0);
            atomicAdd(&g_qbar[c * 1024 + t + 512], qbr1);
            qbr0 = 0.0f; qbr1 = 0.0f;
            __syncthreads();   // commitment reads of red/cb done block-wide
            const float4* cb4 = (const float4*)(cbg + (size_t)nc * (KK * 32));
            #pragma unroll
            for (int it = 0; it < 16; it++) {
                int i = t + it * THREADS;
                float4 v = cb4[i];
                int k = i >> 3, j4 = i & 7;
                *(float4*)(cbb + k * 128 + ((j4 * 16) ^ ((k & 7) << 4))) = v;
            }
            __syncthreads();
            #pragma unroll
            for (int m = 0; m < 2; m++) {
                int k = t + 512 * m;
                float sq = 0.0f;
                #pragma unroll
                for (int j4 = 0; j4 < 8; j4++) {
                    float4 v = *cb_vec(cbb, k, j4);
                    sq += v.x * v.x + v.y * v.y + v.z * v.z + v.w * v.w;
                }
                cq[m] = sq;
            }
            c = nc;
        }
    }

    // ---- flush accumulators ----
    #pragma unroll
    for (int off = 16; off; off >>= 1) {
        ct_comm += __shfl_xor_sync(0xffffffffu, ct_comm, off);
        zsq_acc += __shfl_xor_sync(0xffffffffu, zsq_acc, off);
    }
    if (lane == 0) {
        atomicAdd(&g_comm, ct_comm);
        atomicAdd(&g_ne, acc_ne);
        atomicAdd(&g_qd, acc_qd + zsq_acc);
    }
    atomicAdd(&g_qbar[c * 1024 + t],       qbr0);
    atomicAdd(&g_qbar[c * 1024 + t + 512], qbr1);

    // ---- last-block finalize (ticket) ----
    __threadfence();
    int* flag = (int*)(sm + OFF_IDX);
    if (t == 0) {
        unsigned int v = atomicAdd(&g_count, 1u);
        flag[16] = (v == (unsigned)(NBLOCKS - 1));
    }
    __syncthreads();
    if (flag[16]) {
        float local = 0.0f;
        for (int i = t; i < CC * KK; i += THREADS) {
            float qb = g_qbar[i] * (1.0f / 4096.0f);
            local += qb * __logf(fmaf(qb, 1024.0f, 1e-8f));
            g_qbar[i] = 0.0f;                   // reset for next graph replay
        }
        #pragma unroll
        for (int off = 16; off; off >>= 1)
            local += __shfl_xor_sync(0xffffffffu, local, off);
        if (lane == 0) scr[w] = local;
        __syncthreads();
        if (t == 0) {
            float s = 0.0f;
            #pragma unroll
            for (int i = 0; i < 16; i++) s += scr[i];
            float balance = s * 0.125f;
            float comm = g_comm * (1.0f / 1048576.0f);
            float mne  = g_ne   * (1.0f / 32768.0f);
            float mqd  = g_qd   * (1.0f / 32768.0f);
            out[O_SC + 0] = comm;
            out[O_SC + 1] = fmaf(mqd, 0.5f, mne) + 6.93147180559945f;
            out[O_SC + 2] = -mne;
            out[O_SC + 3] = balance;
            out[O_SC + 4] = 1.0f;
            g_comm = 0.0f; g_ne = 0.0f; g_qd = 0.0f;
            g_count = 0u;
        }
    }
}

extern "C" void kernel_launch(void* const* d_in, const int* in_sizes, int n_in,
                              void* d_out, int out_size)
{
    const float* z   = (const float*)d_in[0];   // (4,256,32,32) f32
    const float* cbg = (const float*)d_in[1];   // (8,1024,32)  f32
    float* out = (float*)d_out;

    cudaFuncSetAttribute(lgq_main, cudaFuncAttributeMaxDynamicSharedMemorySize,
                         SMEM_BYTES);
    lgq_main<<<NBLOCKS, THREADS, SMEM_BYTES>>>(z, cbg, out);
}

// round 7
// speedup vs baseline: 1.4094x; 1.0611x over previous
#include <cuda_runtime.h>

typedef unsigned long long u64;

// ---------------- problem constants ----------------
#define CC 8
#define KK 1024
#define NT 16
#define TILES 256              // 4096 / NT
#define THREADS 512
#define NBLOCKS 148            // one block per SM, contiguous task ranges

// ---------------- smem layout (float offsets) ----------------
#define OFF_CB   0             // 32768: 1024 rows x 128B, SW128-swizzled
#define OFF_DS   32768         // 16384: [16 n][1024 k]  dists -> q (col-swizzled)
#define OFF_ZFT  49152         // 1024:  2 x [32 j][16 n]
#define OFF_ZFTT 50176         // 1056:  2 x [16 n][stride 33 j]  (transposed)
#define OFF_RED  51232         // 4096:  [8 slab][16 n][32 j]  (single buffer)
#define OFF_SCR  55328         // 16
#define OFF_IDX  55344         // 24 ints
#define SMEM_FLOATS 55368
#define SMEM_BYTES (SMEM_FLOATS * 4)   // 221472 B

// ---------------- output packing (float32, tuple order) ----------------
#define O_IDX   1048576u
#define O_Q     1081344u
#define O_SC    34635776u

// ---------------- global scratch ----------------
__device__ float g_qbar[CC * KK];
__device__ float g_comm;
__device__ float g_ne;
__device__ float g_qd;
__device__ unsigned int g_count;

// ---------------- f32x2 helpers ----------------
__device__ __forceinline__ void fma2(u64 &d, u64 a, u64 b) {
    asm("fma.rn.f32x2 %0, %1, %2, %0;" : "+l"(d) : "l"(a), "l"(b));
}
__device__ __forceinline__ u64 add2(u64 a, u64 b) {
    u64 r; asm("add.rn.f32x2 %0, %1, %2;" : "=l"(r) : "l"(a), "l"(b)); return r;
}
__device__ __forceinline__ u64 dup2(float x) {
    u64 r; asm("mov.b64 %0, {%1, %1};" : "=l"(r) : "f"(x)); return r;
}
__device__ __forceinline__ u64 pk2(float lo, float hi) {
    u64 r; asm("mov.b64 %0, {%1, %2};" : "=l"(r) : "f"(lo), "f"(hi)); return r;
}
__device__ __forceinline__ void unpk2(u64 v, float &lo, float &hi) {
    asm("mov.b64 {%0, %1}, %2;" : "=f"(lo), "=f"(hi) : "l"(v));
}
__device__ __forceinline__ u64 shfl_xor64(u64 v, int m) {
    return __shfl_xor_sync(0xffffffffu, v, m);
}

// ---------------- swizzled codebook addressing (128B rows, SW128) ----------
__device__ __forceinline__ const float4* cb_vec(const char* cbb, int k, int j4) {
    return (const float4*)(cbb + k * 128 + ((j4 * 16) ^ ((k & 7) << 4)));
}
__device__ __forceinline__ float cb_el(const char* cbb, int k, int j) {
    return *(const float*)(cbb + k * 128 + ((j * 4) ^ ((k & 7) << 4)));
}

// ds column swizzle (float index involution): xor bits[3:2] with bits[6:5]
__device__ __forceinline__ int dsx(int i) { return i ^ ((i >> 3) & 12); }

__global__ void __launch_bounds__(THREADS, 1)
lgq_main(const float* __restrict__ z, const float* __restrict__ cbg,
         float* __restrict__ out)
{
    extern __shared__ float sm[];
    char*  cbb  = (char*)sm;
    float* ds   = sm + OFF_DS;
    float* zft  = sm + OFF_ZFT;
    float* zftT = sm + OFF_ZFTT;
    float* red  = sm + OFF_RED;
    float* scr  = sm + OFF_SCR;
    int*   idxs = (int*)(sm + OFF_IDX);

    const int t    = threadIdx.x;
    const int w    = t >> 5;
    const int lane = t & 31;
    const int bx   = blockIdx.x;
    const int jj   = t >> 4;       // staging j (0..31)
    const int ni   = t & 15;       // staging n-within-tile (0..15)

    // ---- contiguous task range: task = (c << 8) | tile ----
    const int start = bx * 13 + min(bx, 124);
    const int gend  = start + 13 + (bx < 124 ? 1 : 0);
    int c = start >> 8;

    float zsq_acc = 0.0f;

    // ---- stage codebook c (swizzled) + zf of first tile ----
    {
        const float4* cb4 = (const float4*)(cbg + (size_t)c * (KK * 32));
        #pragma unroll
        for (int it = 0; it < 16; it++) {
            int i = t + it * THREADS;
            float4 v = cb4[i];
            int k = i >> 3, j4 = i & 7;
            *(float4*)(cbb + k * 128 + ((j4 * 16) ^ ((k & 7) << 4))) = v;
        }
        int n = (start & 255) * NT + ni;
        int b = n >> 10;
        float v = z[(size_t)(b * 256 + c * 32 + jj) * 1024 + (n & 1023)];
        zft[jj * 16 + ni]  = v;
        zftT[ni * 33 + jj] = v;
        zsq_acc += v * v;
    }
    __syncthreads();

    // ---- codeword norms for k = t, t+512 ----
    float cq[2];
    #pragma unroll
    for (int m = 0; m < 2; m++) {
        int k = t + 512 * m;
        float s = 0.0f;
        #pragma unroll
        for (int j4 = 0; j4 < 8; j4++) {
            float4 v = *cb_vec(cbb, k, j4);
            s += v.x * v.x + v.y * v.y + v.z * v.z + v.w * v.w;
        }
        cq[m] = s;
    }

    // swizzled ds float index for this thread's k = t (and +512)
    const int kx0 = dsx(t);            // dsx(t+512) == kx0 + 512
    // swizzled float4-chunk base for phase-2 (constant per lane)
    const int lx  = lane ^ ((lane >> 3) & 3);

    float ct_comm = 0.0f;
    float acc_ne = 0.0f, acc_qd = 0.0f;
    float qbr0 = 0.0f, qbr1 = 0.0f;
    int buf = 0;

    for (int gi = start; gi < gend; gi++) {
        const int nb = (gi & 255) * NT;

        // ---- prefetch next task's zf (may be a different c) ----
        const int gn = gi + 1;
        const bool has_next = (gn < gend);
        const int nc = gn >> 8;
        float zn = 0.0f;
        if (has_next) {
            int n = (gn & 255) * NT + ni;
            int b = n >> 10;
            zn = z[(size_t)(b * 256 + nc * 32 + jj) * 1024 + (n & 1023)];
        }

        // ================= phase 1: r = cbsq - 2*cross via f32x2 ==========
        {
            u64 acc[8][2];
            #pragma unroll
            for (int np = 0; np < 8; np++) { acc[np][0] = 0ull; acc[np][1] = 0ull; }

            const int sx = (t & 7) << 4;
            const float* zb = zft + buf * 512;

            #pragma unroll
            for (int j4 = 0; j4 < 8; j4++) {
                const int off = (j4 * 16) ^ sx;
                float4 cv0 = *(const float4*)(cbb + t * 128 + off);
                float4 cv1 = *(const float4*)(cbb + (t + 512) * 128 + off);
                #pragma unroll
                for (int e = 0; e < 4; e++) {
                    int j = j4 * 4 + e;
                    const ulonglong2* zp = (const ulonglong2*)(zb + j * 16);
                    ulonglong2 zA = zp[0], zB = zp[1];
                    ulonglong2 zC = zp[2], zD = zp[3];
                    float e0 = (e == 0) ? cv0.x : (e == 1) ? cv0.y
                             : (e == 2) ? cv0.z : cv0.w;
                    float e1 = (e == 0) ? cv1.x : (e == 1) ? cv1.y
                             : (e == 2) ? cv1.z : cv1.w;
                    u64 d0 = dup2(e0), d1 = dup2(e1);
                    fma2(acc[0][0], zA.x, d0); fma2(acc[0][1], zA.x, d1);
                    fma2(acc[1][0], zA.y, d0); fma2(acc[1][1], zA.y, d1);
                    fma2(acc[2][0], zB.x, d0); fma2(acc[2][1], zB.x, d1);
                    fma2(acc[3][0], zB.y, d0); fma2(acc[3][1], zB.y, d1);
                    fma2(acc[4][0], zC.x, d0); fma2(acc[4][1], zC.x, d1);
                    fma2(acc[5][0], zC.y, d0); fma2(acc[5][1], zC.y, d1);
                    fma2(acc[6][0], zD.x, d0); fma2(acc[6][1], zD.x, d1);
                    fma2(acc[7][0], zD.y, d0); fma2(acc[7][1], zD.y, d1);
                }
            }
            #pragma unroll
            for (int np = 0; np < 8; np++)
                #pragma unroll
                for (int m = 0; m < 2; m++) {
                    float a, b2; unpk2(acc[np][m], a, b2);
                    int k = kx0 + 512 * m;      // swizzled column
                    ds[(2 * np) * 1024 + k]     = fmaf(-2.0f, a,  cq[m]);
                    ds[(2 * np + 1) * 1024 + k] = fmaf(-2.0f, b2, cq[m]);
                }
        }
        __syncthreads();

        // ========== phase 2: single-pass softmax / argmin (n = nb + w) ====
        {
            float* row = ds + w * 1024;
            const float4* row4  = (const float4*)row;
            float4*       row4w = (float4*)row;
            float dv[32];
            #pragma unroll
            for (int m4 = 0; m4 < 8; m4++) {
                float4 v = row4[lx + 32 * m4];   // de-swizzled -> canonical chunk
                dv[m4 * 4 + 0] = v.x; dv[m4 * 4 + 1] = v.y;
                dv[m4 * 4 + 2] = v.z; dv[m4 * 4 + 3] = v.w;
            }
            float rmin = 3.4e38f; int kmin = 1 << 30;
            #pragma unroll
            for (int i = 0; i < 32; i++) {
                int k = 4 * lane + 128 * (i >> 2) + (i & 3);
                float dd = dv[i];
                if (dd < rmin || (dd == rmin && k < kmin)) { rmin = dd; kmin = k; }
            }
            #pragma unroll
            for (int off = 16; off; off >>= 1) {
                float od = __shfl_xor_sync(0xffffffffu, rmin, off);
                int   ok = __shfl_xor_sync(0xffffffffu, kmin, off);
                if (od < rmin || (od == rmin && ok < kmin)) { rmin = od; kmin = ok; }
            }
            float Z = 0.0f, sed = 0.0f;
            #pragma unroll
            for (int i = 0; i < 32; i++) {
                float told = dv[i];
                float ev = __expf((rmin - told) * 0.5f);
                Z += ev;
                sed = fmaf(ev, told, sed);
                dv[i] = ev;
            }
            #pragma unroll
            for (int off = 16; off; off >>= 1) {
                Z   += __shfl_xor_sync(0xffffffffu, Z, off);
                sed += __shfl_xor_sync(0xffffffffu, sed, off);
            }
            float rZ = __fdividef(1.0f, Z);
            float qd = sed * rZ;

            int n = nb + w;
            float4* gq4 = (float4*)(out + O_Q + ((size_t)n * 8 + c) * 1024);
            #pragma unroll
            for (int m4 = 0; m4 < 8; m4++) {
                float4 qv;
                qv.x = dv[m4 * 4 + 0] * rZ; qv.y = dv[m4 * 4 + 1] * rZ;
                qv.z = dv[m4 * 4 + 2] * rZ; qv.w = dv[m4 * 4 + 3] * rZ;
                row4w[lx + 32 * m4]   = qv;   // q -> smem (swizzled pos)
                gq4[lane + 32 * m4]   = qv;   // q -> global (canonical)
            }
            if (lane == 0) {
                acc_ne += 0.5f * (rmin - qd) - __logf(Z);
                acc_qd += qd;
                idxs[w] = kmin;
            }
        }
        __syncthreads();

        // ========== phase 3: zq with 2-D lane split (ks x jg) =============
        {
            const int s  = w & 7;          // k slab [s*128, s*128+128)
            const int nh = (w >> 3) * 8;   // n half
            const int ks = lane >> 3;      // k sub-chunk (32 k)
            const int jg = lane & 7;       // j group of 4

            u64 acc[8][2];
            #pragma unroll
            for (int n2 = 0; n2 < 8; n2++) { acc[n2][0] = 0ull; acc[n2][1] = 0ull; }

            #pragma unroll
            for (int i4 = 0; i4 < 8; i4++) {
                const int kb = s * 128 + ks * 32 + i4 * 4;
                u64 cj0[4], cj1[4];
                #pragma unroll
                for (int e = 0; e < 4; e++) {
                    const float4 v = *(const float4*)(cbb + (kb + e) * 128 +
                        ((jg * 16) ^ (((kb + e) & 7) << 4)));
                    cj0[e] = pk2(v.x, v.y);
                    cj1[e] = pk2(v.z, v.w);
                }
                const int qc = (kb >> 2) ^ ks;   // swizzled float4 chunk
                #pragma unroll
                for (int n2 = 0; n2 < 8; n2++) {
                    const float4 qv = ((const float4*)ds)[(nh + n2) * 256 + qc];
                    u64 dx = dup2(qv.x), dy = dup2(qv.y);
                    u64 dz = dup2(qv.z), dw2 = dup2(qv.w);
                    fma2(acc[n2][0], dx,  cj0[0]); fma2(acc[n2][1], dx,  cj1[0]);
                    fma2(acc[n2][0], dy,  cj0[1]); fma2(acc[n2][1], dy,  cj1[1]);
                    fma2(acc[n2][0], dz,  cj0[2]); fma2(acc[n2][1], dz,  cj1[2]);
                    fma2(acc[n2][0], dw2, cj0[3]); fma2(acc[n2][1], dw2, cj1[3]);
                }
            }
            // reduce across ks (lane bits 3,4)
            #pragma unroll
            for (int n2 = 0; n2 < 8; n2++) {
                acc[n2][0] = add2(acc[n2][0], shfl_xor64(acc[n2][0], 8));
                acc[n2][1] = add2(acc[n2][1], shfl_xor64(acc[n2][1], 8));
                acc[n2][0] = add2(acc[n2][0], shfl_xor64(acc[n2][0], 16));
                acc[n2][1] = add2(acc[n2][1], shfl_xor64(acc[n2][1], 16));
            }
            // each ks lane stores its 2 n rows (4 j each)
            #pragma unroll
            for (int u2 = 0; u2 < 2; u2++) {
                int n2 = ks * 2 + u2;
                float a0, a1, a2, a3;
                unpk2(acc[n2][0], a0, a1);
                unpk2(acc[n2][1], a2, a3);
                *(float4*)(red + s * 512 + (nh + n2) * 32 + jg * 4) =
                    make_float4(a0, a1, a2, a3);
            }

            // qbar partials (canonical k = t, t+512; swizzled columns)
            float s0 = 0.0f, s1 = 0.0f;
            #pragma unroll
            for (int n2 = 0; n2 < 16; n2++) {
                s0 += ds[n2 * 1024 + kx0];
                s1 += ds[n2 * 1024 + kx0 + 512];
            }
            qbr0 += s0; qbr1 += s1;

            {
                int n = nb + ni;
                int b = n >> 10;
                int kq = idxs[ni];
                out[(size_t)(b * 256 + c * 32 + jj) * 1024 + (n & 1023)] =
                    cb_el(cbb, kq, jj);
            }
            if (t < 16) {
                int n = nb + t;
                int b = n >> 10;
                out[O_IDX + (size_t)b * 8192 + c * 1024 + (n & 1023)] =
                    (float)idxs[t];
            }
            if (has_next) {
                zft[(buf ^ 1) * 512 + jj * 16 + ni]  = zn;
                zftT[(buf ^ 1) * 528 + ni * 33 + jj] = zn;
                zsq_acc += zn * zn;
            }
        }
        __syncthreads();

        // ========== commitment: t <-> (n = w, j = lane), conflict-free ====
        {
            float s = 0.0f;
            #pragma unroll
            for (int ss = 0; ss < 8; ss++) s += red[ss * 512 + w * 32 + lane];
            float diff = zftT[buf * 528 + w * 33 + lane] - s;
            ct_comm = fmaf(diff, diff, ct_comm);
        }
        buf ^= 1;

        // ---- codebook switch (at most once per block) ----
        if (has_next && nc != c) {
            atomicAdd(&g_qbar[c * 1024 + t],       qbr0);
            atomicAdd(&g_qbar[c * 1024 + t + 512], qbr1);
            qbr0 = 0.0f; qbr1 = 0.0f;
            __syncthreads();
            const float4* cb4 = (const float4*)(cbg + (size_t)nc * (KK * 32));
            #pragma unroll
            for (int it = 0; it < 16; it++) {
                int i = t + it * THREADS;
                float4 v = cb4[i];
                int k = i >> 3, j4 = i & 7;
                *(float4*)(cbb + k * 128 + ((j4 * 16) ^ ((k & 7) << 4))) = v;
            }
            __syncthreads();
            #pragma unroll
            for (int m = 0; m < 2; m++) {
                int k = t + 512 * m;
                float sq = 0.0f;
                #pragma unroll
                for (int j4 = 0; j4 < 8; j4++) {
                    float4 v = *cb_vec(cbb, k, j4);
                    sq += v.x * v.x + v.y * v.y + v.z * v.z + v.w * v.w;
                }
                cq[m] = sq;
            }
            c = nc;
        }
    }

    // ---- flush accumulators ----
    #pragma unroll
    for (int off = 16; off; off >>= 1) {
        ct_comm += __shfl_xor_sync(0xffffffffu, ct_comm, off);
        zsq_acc += __shfl_xor_sync(0xffffffffu, zsq_acc, off);
    }
    if (lane == 0) {
        atomicAdd(&g_comm, ct_comm);
        atomicAdd(&g_ne, acc_ne);
        atomicAdd(&g_qd, acc_qd + zsq_acc);
    }
    atomicAdd(&g_qbar[c * 1024 + t],       qbr0);
    atomicAdd(&g_qbar[c * 1024 + t + 512], qbr1);

    // ---- last-block finalize (ticket) ----
    __threadfence();
    int* flag = (int*)(sm + OFF_IDX);
    if (t == 0) {
        unsigned int v = atomicAdd(&g_count, 1u);
        flag[16] = (v == (unsigned)(NBLOCKS - 1));
    }
    __syncthreads();
    if (flag[16]) {
        float local = 0.0f;
        for (int i = t; i < CC * KK; i += THREADS) {
            float qb = g_qbar[i] * (1.0f / 4096.0f);
            local += qb * __logf(fmaf(qb, 1024.0f, 1e-8f));
            g_qbar[i] = 0.0f;                   // reset for next graph replay
        }
        #pragma unroll
        for (int off = 16; off; off >>= 1)
            local += __shfl_xor_sync(0xffffffffu, local, off);
        if (lane == 0) scr[w] = local;
        __syncthreads();
        if (t == 0) {
            float s = 0.0f;
            #pragma unroll
            for (int i = 0; i < 16; i++) s += scr[i];
            float balance = s * 0.125f;
            float comm = g_comm * (1.0f / 1048576.0f);
            float mne  = g_ne   * (1.0f / 32768.0f);
            float mqd  = g_qd   * (1.0f / 32768.0f);
            out[O_SC + 0] = comm;
            out[O_SC + 1] = fmaf(mqd, 0.5f, mne) + 6.93147180559945f;
            out[O_SC + 2] = -mne;
            out[O_SC + 3] = balance;
            out[O_SC + 4] = 1.0f;
            g_comm = 0.0f; g_ne = 0.0f; g_qd = 0.0f;
            g_count = 0u;
        }
    }
}

extern "C" void kernel_launch(void* const* d_in, const int* in_sizes, int n_in,
                              void* d_out, int out_size)
{
    const float* z   = (const float*)d_in[0];   // (4,256,32,32) f32
    const float* cbg = (const float*)d_in[1];   // (8,1024,32)  f32
    float* out = (float*)d_out;

    cudaFuncSetAttribute(lgq_main, cudaFuncAttributeMaxDynamicSharedMemorySize,
                         SMEM_BYTES);
    lgq_main<<<NBLOCKS, THREADS, SMEM_BYTES>>>(z, cbg, out);
}